// round 14
// baseline (speedup 1.0000x reference)
#include <cuda_runtime.h>
#include <cuda_fp16.h>
#include <cstdint>

// Model_53283364274775 on GB300 (plain sm_103 PTX target -> no tcgen05):
// single fused kernel. Block roles by bid (dependency order == bid order):
//   [0,192)    prep: build W0/W1 mma B-fragment images (rel 0..2 AO, 3 UI)
//   [192,256)  ui:   2-layer MLP for user/item pairs (waits prep)
//   [256,1280) scatter: warp-aggregated relation bucket sort
//   [1280,...) ao:   2-layer MLP + dot (waits scatter; waits ui pre-dot)
// Flag sync via g_sync counters, reset each call by cudaMemsetAsync.

#define B_   8192
#define N_   32
#define TOT  (B_ * N_)          // 262144 = 2^18
#define SLOPE 0.01f

#define NPREP 192
#define NUI   64
#define NSCAT 1024
#define NAO   6144
#define NGRID (NPREP + NUI + NSCAT + NAO)

// g_sync: [0]=prep_done [1]=ui_done [2]=scat_done [3] pad [4..6]=cnt[3] [7] pad
__device__ int   g_sync[8];
__device__ int   g_perm[3 * TOT];
__device__ float g_ui[B_ * 64];
// W0 B-fragments: [rel][kk(8)][j2(8)][lane] uint4  (32KB/rel)
__device__ uint4 g_w0frag[4 * 8 * 8 * 32];
// W1 B-fragments: [rel][kk(8)][q(4)][lane] uint4   (16KB/rel)
__device__ uint4 g_w1frag[4 * 8 * 4 * 32];

__device__ __forceinline__ float lrelu(float x) { return x >= 0.f ? x : SLOPE * x; }

__device__ __forceinline__ uint32_t smem_to_u32(const void* p) {
    uint32_t a;
    asm("{ .reg .u64 t; cvta.to.shared.u64 t, %1; cvt.u32.u64 %0, t; }"
        : "=r"(a) : "l"(p));
    return a;
}
__device__ __forceinline__ void ldsm_x4(uint32_t& r0, uint32_t& r1,
                                        uint32_t& r2, uint32_t& r3, uint32_t addr) {
    asm volatile("ldmatrix.sync.aligned.m8n8.x4.shared.b16 {%0,%1,%2,%3}, [%4];"
        : "=r"(r0), "=r"(r1), "=r"(r2), "=r"(r3) : "r"(addr));
}
__device__ __forceinline__ void mma_f16(float* d, const uint32_t* a4,
                                        uint32_t b0, uint32_t b1) {
    asm volatile("mma.sync.aligned.m16n8k16.row.col.f32.f16.f16.f32 "
        "{%0,%1,%2,%3}, {%4,%5,%6,%7}, {%8,%9}, {%0,%1,%2,%3};"
        : "+f"(d[0]), "+f"(d[1]), "+f"(d[2]), "+f"(d[3])
        : "r"(a4[0]), "r"(a4[1]), "r"(a4[2]), "r"(a4[3]), "r"(b0), "r"(b1));
}
__device__ __forceinline__ uint32_t sw_off(int row, int chunk16) {
    return (uint32_t)(row * 256 + ((chunk16 ^ (row & 7)) << 4));
}
__device__ __forceinline__ uint32_t pack2h(float f0, float f1) {
    return (uint32_t)__half_as_ushort(__float2half_rn(f0)) |
           ((uint32_t)__half_as_ushort(__float2half_rn(f1)) << 16);
}
// producer: all block work done -> fence + count
__device__ __forceinline__ void signal_done(int* ctr) {
    __syncthreads();
    if (threadIdx.x == 0) { __threadfence(); atomicAdd(ctr, 1); }
}
// consumer: tid0 polls, fence, block barrier
__device__ __forceinline__ void wait_for(int* ctr, int target) {
    if (threadIdx.x == 0) {
        while (atomicAdd(ctr, 0) < target) __nanosleep(128);
        __threadfence();
    }
    __syncthreads();
}

// smem layout (bytes): b0 @0 (512) | b1 @512 (256) | pad | X @1024 (32K+2K)
#define OFF_B0   0
#define OFF_B1   512
#define OFF_X    1024
#define SM_BYTES 35840

// ======================= core: two layers, register H ======================
__device__ __forceinline__ void two_layer_reg(
    char* smem, uint32_t smem_base, int rel, int lane, int wid,
    float (&acc2)[8][4])
{
    const float* sb0 = (const float*)(smem + OFF_B0);
    uint32_t afrag2[8][4];
    const uint32_t Ab = smem_base + OFF_X;
    const int arow = wid * 16 + (lane & 15);

    #pragma unroll
    for (int h = 0; h < 2; h++) {
        float acc[8][4];
        #pragma unroll
        for (int j = 0; j < 8; j++)
            #pragma unroll
            for (int q = 0; q < 4; q++) acc[j][q] = 0.f;

        const uint4* w0p = g_w0frag + (((size_t)rel * 8) * 8 + h * 4) * 32 + lane;
        #pragma unroll
        for (int kk = 0; kk < 8; kk++) {
            uint4 bq[4];
            #pragma unroll
            for (int q = 0; q < 4; q++) bq[q] = w0p[(kk * 8 + q) * 32];
            uint32_t af[4];
            ldsm_x4(af[0], af[1], af[2], af[3],
                    Ab + sw_off(arow, kk * 2 + (lane >> 4)));
            #pragma unroll
            for (int j = 0; j < 8; j++)
                mma_f16(acc[j], af,
                        (j & 1) ? bq[j >> 1].z : bq[j >> 1].x,
                        (j & 1) ? bq[j >> 1].w : bq[j >> 1].y);
        }

        #pragma unroll
        for (int q2 = 0; q2 < 4; q2++) {
            int c0 = h * 64 + q2 * 16 + 2 * (lane & 3);
            float b00 = sb0[c0],     b01 = sb0[c0 + 1];
            float b80 = sb0[c0 + 8], b81 = sb0[c0 + 9];
            afrag2[h * 4 + q2][0] =
                pack2h(lrelu(acc[2 * q2][0] + b00), lrelu(acc[2 * q2][1] + b01));
            afrag2[h * 4 + q2][1] =
                pack2h(lrelu(acc[2 * q2][2] + b00), lrelu(acc[2 * q2][3] + b01));
            afrag2[h * 4 + q2][2] =
                pack2h(lrelu(acc[2 * q2 + 1][0] + b80), lrelu(acc[2 * q2 + 1][1] + b81));
            afrag2[h * 4 + q2][3] =
                pack2h(lrelu(acc[2 * q2 + 1][2] + b80), lrelu(acc[2 * q2 + 1][3] + b81));
        }
    }

    #pragma unroll
    for (int j = 0; j < 8; j++)
        #pragma unroll
        for (int q = 0; q < 4; q++) acc2[j][q] = 0.f;

    const uint4* w1p = g_w1frag + ((size_t)rel * 8) * 4 * 32 + lane;
    #pragma unroll
    for (int c = 0; c < 8; c++) {
        uint4 bq[4];
        #pragma unroll
        for (int q = 0; q < 4; q++) bq[q] = w1p[(c * 4 + q) * 32];
        #pragma unroll
        for (int j = 0; j < 8; j++)
            mma_f16(acc2[j], afrag2[c],
                    (j & 1) ? bq[j >> 1].z : bq[j >> 1].x,
                    (j & 1) ? bq[j >> 1].w : bq[j >> 1].y);
    }
}

__device__ __forceinline__ void load_bias(char* smem, int tid,
                                          const float* b0, const float* b1) {
    if (tid < 128) ((float*)(smem + OFF_B0))[tid] = b0[tid];
    if (tid < 64)  ((float*)(smem + OFF_B1))[tid] = b1[tid];
}

// ======================= THE fused kernel ==================================
__global__ void __launch_bounds__(256, 2) fused_kernel(
    const float* __restrict__ u, const float* __restrict__ iv,
    const float* __restrict__ a, const float* __restrict__ o,
    const int* __restrict__ s_raw,
    const float* __restrict__ aoW0, const float* __restrict__ aob0,
    const float* __restrict__ aoW1, const float* __restrict__ aob1,
    const float* __restrict__ uiW0, const float* __restrict__ uib0,
    const float* __restrict__ uiW1, const float* __restrict__ uib1,
    float* __restrict__ out)
{
    extern __shared__ char smem[];
    const int bid = blockIdx.x;
    const int tid = threadIdx.x;

    // ---------------- prep: [0, NPREP) --------------------------------
    if (bid < NPREP) {
        int idx = bid * 256 + tid;             // 0..49151
        if (idx < 32768) {
            int r = idx >> 13, t = idx & 8191;
            int w    = t & 3;
            int lane = (t >> 2) & 31;
            int j2   = (t >> 7) & 7;
            int kk   = (t >> 10) & 7;
            const float* W = (r < 3) ? (aoW0 + r * 16384) : uiW0;
            int j = 2 * j2 + (w >> 1);
            int n = j * 8 + (lane >> 2);
            int k = kk * 16 + (lane & 3) * 2 + (w & 1) * 8;
            uint32_t v = pack2h(W[k * 128 + n], W[(k + 1) * 128 + n]);
            ((uint32_t*)g_w0frag)[((((size_t)r * 8 + kk) * 8 + j2) * 32 + lane) * 4 + w] = v;
        } else {
            int t2 = idx - 32768;
            int r = t2 >> 12, t = t2 & 4095;
            int w    = t & 3;
            int lane = (t >> 2) & 31;
            int q    = (t >> 7) & 3;
            int kk   = (t >> 9) & 7;
            const float* W = (r < 3) ? (aoW1 + r * 8192) : uiW1;
            int j = 2 * q + (w >> 1);
            int n = j * 8 + (lane >> 2);
            int k = kk * 16 + (lane & 3) * 2 + (w & 1) * 8;
            uint32_t v = pack2h(W[k * 64 + n], W[(k + 1) * 64 + n]);
            ((uint32_t*)g_w1frag)[((((size_t)r * 8 + kk) * 4 + q) * 32 + lane) * 4 + w] = v;
        }
        signal_done(&g_sync[0]);
        return;
    }

    // ---------------- ui: [NPREP, NPREP+NUI) --------------------------
    if (bid < NPREP + NUI) {
        const uint32_t smem_base = smem_to_u32(smem);
        const int lane = tid & 31;
        const int wid = tid >> 5;
        const int rowbase = (bid - NPREP) * 128;

        load_bias(smem, tid, uib0, uib1);
        {
            const int xrow = tid >> 1;
            const int half = tid & 1;
            const float* src = (half ? iv : u) + (size_t)(rowbase + xrow) * 64;
            #pragma unroll
            for (int j = 0; j < 8; j++) {
                float4 v0 = ((const float4*)src)[2 * j];
                float4 v1 = ((const float4*)src)[2 * j + 1];
                uint32_t off = sw_off(xrow, half * 8 + j);
                *(uint4*)(smem + OFF_X + off) = make_uint4(
                    pack2h(v0.x, v0.y), pack2h(v0.z, v0.w),
                    pack2h(v1.x, v1.y), pack2h(v1.z, v1.w));
            }
        }
        wait_for(&g_sync[0], NPREP);    // fragments ready (also syncs smem X)

        float acc2[8][4];
        two_layer_reg(smem, smem_base, 3, lane, wid, acc2);

        const float* sb1 = (const float*)(smem + OFF_B1);
        int row0 = wid * 16 + (lane >> 2);
        #pragma unroll
        for (int j = 0; j < 8; j++) {
            int col = j * 8 + 2 * (lane & 3);
            float bv0 = sb1[col], bv1 = sb1[col + 1];
            *(float2*)&g_ui[(size_t)(rowbase + row0) * 64 + col] =
                make_float2(lrelu(acc2[j][0] + bv0), lrelu(acc2[j][1] + bv1));
            *(float2*)&g_ui[(size_t)(rowbase + row0 + 8) * 64 + col] =
                make_float2(lrelu(acc2[j][2] + bv0), lrelu(acc2[j][3] + bv1));
        }
        signal_done(&g_sync[1]);
        return;
    }

    // ---------------- scatter: [NPREP+NUI, NPREP+NUI+NSCAT) -----------
    if (bid < NPREP + NUI + NSCAT) {
        __shared__ int sIs64;
        if (tid == 0) {
            int nz = 0;
            #pragma unroll
            for (int i = 1; i < 256; i += 2) nz |= s_raw[i];
            sIs64 = (nz == 0) ? 1 : 0;
        }
        __syncthreads();
        int idx = (bid - NPREP - NUI) * 256 + tid;
        int lane = tid & 31;
        int r = sIs64 ? s_raw[2 * idx] : s_raw[idx];
        unsigned m0 = __ballot_sync(0xffffffffu, r == 0);
        unsigned m1 = __ballot_sync(0xffffffffu, r == 1);
        unsigned mine = (r == 0) ? m0 : (r == 1) ? m1 : ~(m0 | m1);
        int leader = __ffs(mine) - 1;
        int base = 0;
        if (lane == leader) base = atomicAdd(&g_sync[4 + r], __popc(mine));
        base = __shfl_sync(0xffffffffu, base, leader);
        g_perm[r * TOT + base + __popc(mine & ((1u << lane) - 1u))] = idx;
        signal_done(&g_sync[2]);
        return;
    }

    // ---------------- ao: [NPREP+NUI+NSCAT, NGRID) --------------------
    {
        const uint32_t smem_base = smem_to_u32(smem);
        const int lane = tid & 31;
        const int wid = tid >> 5;
        const int slotbase = (bid - NPREP - NUI - NSCAT) * 128;  // in [0,3*TOT)
        const int r = slotbase >> 18;
        const int local = slotbase & (TOT - 1);

        wait_for(&g_sync[2], NSCAT);    // perm + counts final

        const int count = g_sync[4 + r];
        if (local >= count) return;
        const int nvalid = min(128, count - local);

        load_bias(smem, tid, aob0 + r * 128, aob1 + r * 64);

        {
            const int xrow = tid >> 1;
            const int half = tid & 1;
            if (xrow < nvalid) {
                const int grow = g_perm[r * TOT + local + xrow];
                const float* src = (half ? o : a) + (size_t)grow * 64;
                #pragma unroll
                for (int j = 0; j < 8; j++) {
                    float4 v0 = ((const float4*)src)[2 * j];
                    float4 v1 = ((const float4*)src)[2 * j + 1];
                    uint32_t off = sw_off(xrow, half * 8 + j);
                    *(uint4*)(smem + OFF_X + off) = make_uint4(
                        pack2h(v0.x, v0.y), pack2h(v0.z, v0.w),
                        pack2h(v1.x, v1.y), pack2h(v1.z, v1.w));
                }
            } else {
                #pragma unroll
                for (int j = 0; j < 8; j++)
                    *(uint4*)(smem + OFF_X + sw_off(xrow, half * 8 + j)) =
                        make_uint4(0, 0, 0, 0);
            }
        }
        __syncthreads();

        float acc2[8][4];
        two_layer_reg(smem, smem_base, r, lane, wid, acc2);
        __syncthreads();                 // all warps done reading X

        // stage D2 (stride 68) into the dead X region
        float* sD2 = (float*)(smem + OFF_X);
        {
            int row0 = wid * 16 + (lane >> 2);
            #pragma unroll
            for (int j = 0; j < 8; j++) {
                int col = j * 8 + 2 * (lane & 3);
                *(float2*)&sD2[row0 * 68 + col] =
                    make_float2(acc2[j][0], acc2[j][1]);
                *(float2*)&sD2[(row0 + 8) * 68 + col] =
                    make_float2(acc2[j][2], acc2[j][3]);
            }
        }
        wait_for(&g_sync[1], NUI);       // g_ui ready (also syncs D2 staging)

        const float* sb1 = (const float*)(smem + OFF_B1);
        if (tid < nvalid) {
            int grow = g_perm[r * TOT + local + tid];
            const float4* uir = (const float4*)(g_ui + (size_t)(grow >> 5) * 64);
            const float* drow = sD2 + tid * 68;
            float sdot = 0.f;
            #pragma unroll
            for (int c4 = 0; c4 < 16; c4++) {
                float4 uv = uir[c4];
                float v0 = lrelu(drow[4 * c4 + 0] + sb1[4 * c4 + 0]);
                float v1 = lrelu(drow[4 * c4 + 1] + sb1[4 * c4 + 1]);
                float v2 = lrelu(drow[4 * c4 + 2] + sb1[4 * c4 + 2]);
                float v3 = lrelu(drow[4 * c4 + 3] + sb1[4 * c4 + 3]);
                sdot = fmaf(v0, uv.x, sdot); sdot = fmaf(v1, uv.y, sdot);
                sdot = fmaf(v2, uv.z, sdot); sdot = fmaf(v3, uv.w, sdot);
            }
            out[grow] = sdot;
        }
    }
}

// ===========================================================================
extern "C" void kernel_launch(void* const* d_in, const int* in_sizes, int n_in,
                              void* d_out, int out_size) {
    const float* u    = (const float*)d_in[0];
    const float* iv   = (const float*)d_in[1];
    const float* a    = (const float*)d_in[2];
    const float* o    = (const float*)d_in[3];
    const int*   s    = (const int*)  d_in[4];
    const float* aoW0 = (const float*)d_in[5];
    const float* aob0 = (const float*)d_in[6];
    const float* aoW1 = (const float*)d_in[7];
    const float* aob1 = (const float*)d_in[8];
    const float* uiW0 = (const float*)d_in[9];
    const float* uib0 = (const float*)d_in[10];
    const float* uiW1 = (const float*)d_in[11];
    const float* uib1 = (const float*)d_in[12];
    float* out = (float*)d_out;

    cudaFuncSetAttribute((const void*)fused_kernel,
                         cudaFuncAttributeMaxDynamicSharedMemorySize, SM_BYTES);

    void* syncp = nullptr;
    cudaGetSymbolAddress(&syncp, g_sync);
    cudaMemsetAsync(syncp, 0, 8 * sizeof(int));

    fused_kernel<<<NGRID, 256, SM_BYTES>>>(
        u, iv, a, o, s, aoW0, aob0, aoW1, aob1, uiW0, uib0, uiW1, uib1, out);
}

// round 15
// speedup vs baseline: 1.0971x; 1.0971x over previous
#include <cuda_runtime.h>
#include <cuda_fp16.h>
#include <cstdint>

// Model_53283364274775 on GB300 (plain sm_103 PTX target -> no tcgen05):
// single-pass fp16 mma.sync. R15: occupancy push. m32n32 warp tiles
// (acc 32 regs) -> <=84 regs -> __launch_bounds__(256,3) -> 24 warps/SM.
// GEMM1 two n64 passes into separate H smem buffer; GEMM2 from H.
// W0/W1 as n32-sliced gmem B-fragments. kk order preserved (bitwise oracle).

#define B_   8192
#define N_   32
#define TOT  (B_ * N_)          // 262144 = 2^18
#define SLOPE 0.01f

__device__ int   g_pos[3];
__device__ int   g_perm[3 * TOT];
__device__ float g_ui[B_ * 64];
// W0 B-fragments: [rel][s(4)][kk(8)][p(2)][lane] uint4   (32KB/rel)
__device__ uint4 g_w0frag[4 * 4 * 8 * 2 * 32];
// W1 B-fragments: [rel][wn2(2)][kk(8)][p(2)][lane] uint4 (16KB/rel)
__device__ uint4 g_w1frag[4 * 2 * 8 * 2 * 32];

__device__ __forceinline__ float lrelu(float x) { return x >= 0.f ? x : SLOPE * x; }

__device__ __forceinline__ uint32_t smem_to_u32(const void* p) {
    uint32_t a;
    asm("{ .reg .u64 t; cvta.to.shared.u64 t, %1; cvt.u32.u64 %0, t; }"
        : "=r"(a) : "l"(p));
    return a;
}
__device__ __forceinline__ void ldsm_x4(uint32_t& r0, uint32_t& r1,
                                        uint32_t& r2, uint32_t& r3, uint32_t addr) {
    asm volatile("ldmatrix.sync.aligned.m8n8.x4.shared.b16 {%0,%1,%2,%3}, [%4];"
        : "=r"(r0), "=r"(r1), "=r"(r2), "=r"(r3) : "r"(addr));
}
__device__ __forceinline__ void mma_f16(float* d, const uint32_t* a4,
                                        uint32_t b0, uint32_t b1) {
    asm volatile("mma.sync.aligned.m16n8k16.row.col.f32.f16.f16.f32 "
        "{%0,%1,%2,%3}, {%4,%5,%6,%7}, {%8,%9}, {%0,%1,%2,%3};"
        : "+f"(d[0]), "+f"(d[1]), "+f"(d[2]), "+f"(d[3])
        : "r"(a4[0]), "r"(a4[1]), "r"(a4[2]), "r"(a4[3]), "r"(b0), "r"(b1));
}
// 256B rows of fp16, XOR swizzle on 16B chunks: conflict-free ldmatrix
__device__ __forceinline__ uint32_t sw_off(int row, int chunk16) {
    return (uint32_t)(row * 256 + ((chunk16 ^ (row & 7)) << 4));
}
__device__ __forceinline__ uint32_t pack2h(float f0, float f1) {
    return (uint32_t)__half_as_ushort(__float2half_rn(f0)) |
           ((uint32_t)__half_as_ushort(__float2half_rn(f1)) << 16);
}

// smem layout (bytes): b0 @0 (512) | b1 @512 (256) | pad |
// X @1024 (32K+2K) | H @35840 (32K+2K).  Total 70656 -> 3 CTAs/SM.
// D2 staging (34816B) reuses the X region after GEMM2.
#define OFF_B0   0
#define OFF_B1   512
#define OFF_X    1024
#define OFF_H    35840
#define SM_BYTES 70656

// ======================= prep_w (+ g_pos init) =============================
__global__ void prep_w_kernel(const float* __restrict__ aoW0,
                              const float* __restrict__ aoW1,
                              const float* __restrict__ uiW0,
                              const float* __restrict__ uiW1) {
    int idx = blockIdx.x * blockDim.x + threadIdx.x;   // 0..49151
    if (blockIdx.x == 0 && threadIdx.x < 3)
        g_pos[threadIdx.x] = threadIdx.x * TOT;

    if (idx < 32768) {
        // W0 frag word: ((((rel*4+s)*8+kk)*2+p)*32+lane)*4+w
        int r = idx >> 13, t = idx & 8191;
        int w    = t & 3;
        int lane = (t >> 2) & 31;
        int p    = (t >> 7) & 1;
        int kk   = (t >> 8) & 7;
        int s    = (t >> 11) & 3;
        const float* W = (r < 3) ? (aoW0 + r * 16384) : uiW0;
        int j = s * 4 + p * 2 + (w >> 1);
        int n = j * 8 + (lane >> 2);
        int k = kk * 16 + (lane & 3) * 2 + (w & 1) * 8;
        uint32_t v = pack2h(W[k * 128 + n], W[(k + 1) * 128 + n]);
        ((uint32_t*)g_w0frag)[(((((size_t)r * 4 + s) * 8 + kk) * 2 + p) * 32 + lane) * 4 + w] = v;
    } else if (idx < 49152) {
        // W1 frag word: ((((rel*2+wn2)*8+kk)*2+p)*32+lane)*4+w
        int t2 = idx - 32768;
        int r = t2 >> 12, t = t2 & 4095;
        int w    = t & 3;
        int lane = (t >> 2) & 31;
        int p    = (t >> 7) & 1;
        int kk   = (t >> 8) & 7;
        int wn2  = (t >> 11) & 1;
        const float* W = (r < 3) ? (aoW1 + r * 8192) : uiW1;
        int j = wn2 * 4 + p * 2 + (w >> 1);
        int n = j * 8 + (lane >> 2);
        int k = kk * 16 + (lane & 3) * 2 + (w & 1) * 8;
        uint32_t v = pack2h(W[k * 64 + n], W[(k + 1) * 64 + n]);
        ((uint32_t*)g_w1frag)[(((((size_t)r * 2 + wn2) * 8 + kk) * 2 + p) * 32 + lane) * 4 + w] = v;
    }
}

// ======================= core: two layers, m32n32 tiles ====================
// Warp grid 4x2: wm2 = wid&3 (m32 rows), wn2 = wid>>2 (n32 of 64).
// GEMM1: two n64 passes (np), slice s = np*2+wn2; H -> OFF_H buffer.
// GEMM2: reads H via ldsm; acc2[2][4][4] = m32 x n32 of D2 (N=64 total).
__device__ __forceinline__ void two_layer_mma(
    char* smem, uint32_t smem_base, int rel, int lane, int wm2, int wn2,
    float (&acc2)[2][4][4])
{
    const float* sb0 = (const float*)(smem + OFF_B0);
    const uint32_t Xb = smem_base + OFF_X;
    const uint32_t Hb = smem_base + OFF_H;

    #pragma unroll
    for (int np = 0; np < 2; np++) {
        float acc[2][4][4];
        #pragma unroll
        for (int i = 0; i < 2; i++)
            #pragma unroll
            for (int j = 0; j < 4; j++)
                #pragma unroll
                for (int q = 0; q < 4; q++) acc[i][j][q] = 0.f;

        const int s = np * 2 + wn2;
        const uint4* w0p = g_w0frag + (((size_t)rel * 4 + s) * 8) * 2 * 32 + lane;
        #pragma unroll
        for (int kk = 0; kk < 8; kk++) {
            uint4 bq[2];
            bq[0] = w0p[(kk * 2 + 0) * 32];
            bq[1] = w0p[(kk * 2 + 1) * 32];
            const int chunk = kk * 2 + (lane >> 4);
            uint32_t af[2][4];
            #pragma unroll
            for (int i = 0; i < 2; i++) {
                int row = wm2 * 32 + i * 16 + (lane & 15);
                ldsm_x4(af[i][0], af[i][1], af[i][2], af[i][3],
                        Xb + sw_off(row, chunk));
            }
            #pragma unroll
            for (int i = 0; i < 2; i++)
                #pragma unroll
                for (int p = 0; p < 2; p++) {
                    mma_f16(acc[i][2 * p],     af[i], bq[p].x, bq[p].y);
                    mma_f16(acc[i][2 * p + 1], af[i], bq[p].z, bq[p].w);
                }
        }

        // epilogue1: H = lrelu(D + b0) -> fp16 into H buffer
        #pragma unroll
        for (int i = 0; i < 2; i++) {
            int row0 = wm2 * 32 + i * 16 + (lane >> 2);
            #pragma unroll
            for (int j = 0; j < 4; j++) {
                int col = np * 64 + wn2 * 32 + j * 8 + 2 * (lane & 3);
                float bv0 = sb0[col], bv1 = sb0[col + 1];
                uint32_t h0 = pack2h(lrelu(acc[i][j][0] + bv0), lrelu(acc[i][j][1] + bv1));
                uint32_t h1 = pack2h(lrelu(acc[i][j][2] + bv0), lrelu(acc[i][j][3] + bv1));
                uint32_t o0 = sw_off(row0, col >> 3) + ((2 * col) & 15);
                uint32_t o1 = sw_off(row0 + 8, col >> 3) + ((2 * col) & 15);
                *(uint32_t*)(smem + OFF_H + o0) = h0;
                *(uint32_t*)(smem + OFF_H + o1) = h1;
            }
        }
    }
    __syncthreads();   // all H written, all X reads done

    // ---- GEMM2: D2 = H @ W1^T ----
    #pragma unroll
    for (int i = 0; i < 2; i++)
        #pragma unroll
        for (int j = 0; j < 4; j++)
            #pragma unroll
            for (int q = 0; q < 4; q++) acc2[i][j][q] = 0.f;

    const uint4* w1p = g_w1frag + (((size_t)rel * 2 + wn2) * 8) * 2 * 32 + lane;
    #pragma unroll
    for (int kk = 0; kk < 8; kk++) {
        uint4 bq[2];
        bq[0] = w1p[(kk * 2 + 0) * 32];
        bq[1] = w1p[(kk * 2 + 1) * 32];
        const int chunk = kk * 2 + (lane >> 4);
        uint32_t af[2][4];
        #pragma unroll
        for (int i = 0; i < 2; i++) {
            int row = wm2 * 32 + i * 16 + (lane & 15);
            ldsm_x4(af[i][0], af[i][1], af[i][2], af[i][3],
                    Hb + sw_off(row, chunk));
        }
        #pragma unroll
        for (int i = 0; i < 2; i++)
            #pragma unroll
            for (int p = 0; p < 2; p++) {
                mma_f16(acc2[i][2 * p],     af[i], bq[p].x, bq[p].y);
                mma_f16(acc2[i][2 * p + 1], af[i], bq[p].z, bq[p].w);
            }
    }
}

__device__ __forceinline__ void load_bias(char* smem, int tid,
                                          const float* b0, const float* b1) {
    if (tid < 128) ((float*)(smem + OFF_B0))[tid] = b0[tid];
    if (tid < 64)  ((float*)(smem + OFF_B1))[tid] = b1[tid];
}

// ======================= UI branch + scatter (fused) =======================
__global__ void __launch_bounds__(256, 3) ui_scatter_kernel(
    const float* __restrict__ u, const float* __restrict__ iv,
    const float* __restrict__ b0, const float* __restrict__ b1,
    const int* __restrict__ s_raw)
{
    extern __shared__ char smem[];
    const int tid = threadIdx.x;

    if (blockIdx.x >= 64) {
        // ---- scatter path (warp-aggregated bucket sort) ----
        __shared__ int sIs64;
        if (tid == 0) {
            int nz = 0;
            #pragma unroll
            for (int i = 1; i < 256; i += 2) nz |= s_raw[i];
            sIs64 = (nz == 0) ? 1 : 0;
        }
        __syncthreads();
        int idx = (blockIdx.x - 64) * 256 + tid;
        int lane = tid & 31;
        int r = sIs64 ? s_raw[2 * idx] : s_raw[idx];
        unsigned m0 = __ballot_sync(0xffffffffu, r == 0);
        unsigned m1 = __ballot_sync(0xffffffffu, r == 1);
        unsigned mine = (r == 0) ? m0 : (r == 1) ? m1 : ~(m0 | m1);
        int leader = __ffs(mine) - 1;
        int base = 0;
        if (lane == leader) base = atomicAdd(&g_pos[r], __popc(mine));
        base = __shfl_sync(0xffffffffu, base, leader);
        g_perm[base + __popc(mine & ((1u << lane) - 1u))] = idx;
        return;
    }

    // ---- UI path ----
    const uint32_t smem_base = smem_to_u32(smem);
    const int lane = tid & 31;
    const int wid = tid >> 5;
    const int wm2 = wid & 3;
    const int wn2 = wid >> 2;
    const int rowbase = blockIdx.x * 128;

    load_bias(smem, tid, b0, b1);
    {
        const int xrow = tid >> 1;
        const int half = tid & 1;
        const float* src = (half ? iv : u) + (size_t)(rowbase + xrow) * 64;
        #pragma unroll
        for (int j = 0; j < 8; j++) {
            float4 v0 = ((const float4*)src)[2 * j];
            float4 v1 = ((const float4*)src)[2 * j + 1];
            uint32_t off = sw_off(xrow, half * 8 + j);
            *(uint4*)(smem + OFF_X + off) = make_uint4(
                pack2h(v0.x, v0.y), pack2h(v0.z, v0.w),
                pack2h(v1.x, v1.y), pack2h(v1.z, v1.w));
        }
    }
    __syncthreads();

    float acc2[2][4][4];
    two_layer_mma(smem, smem_base, 3, lane, wm2, wn2, acc2);

    // epilogue: g_ui = lrelu(D2 + b1) straight from fragments
    const float* sb1 = (const float*)(smem + OFF_B1);
    #pragma unroll
    for (int i = 0; i < 2; i++) {
        int row0 = wm2 * 32 + i * 16 + (lane >> 2);
        #pragma unroll
        for (int j = 0; j < 4; j++) {
            int col = wn2 * 32 + j * 8 + 2 * (lane & 3);
            float bv0 = sb1[col], bv1 = sb1[col + 1];
            *(float2*)&g_ui[(size_t)(rowbase + row0) * 64 + col] =
                make_float2(lrelu(acc2[i][j][0] + bv0), lrelu(acc2[i][j][1] + bv1));
            *(float2*)&g_ui[(size_t)(rowbase + row0 + 8) * 64 + col] =
                make_float2(lrelu(acc2[i][j][2] + bv0), lrelu(acc2[i][j][3] + bv1));
        }
    }
}

// ======================= AO branch: 128 rows per CTA =======================
// 3*TOT/128 = 6144 CTAs; empty tails exit immediately.
__global__ void __launch_bounds__(256, 3) ao_mma_kernel(
    const float* __restrict__ a, const float* __restrict__ o,
    const float* __restrict__ b0, const float* __restrict__ b1,
    float* __restrict__ out)
{
    extern __shared__ char smem[];
    const uint32_t smem_base = smem_to_u32(smem);
    const int tid = threadIdx.x;
    const int lane = tid & 31;
    const int wid = tid >> 5;
    const int wm2 = wid & 3;
    const int wn2 = wid >> 2;
    const int slotbase = blockIdx.x * 128;      // absolute in [0, 3*TOT)
    const int r = slotbase >> 18;               // TOT = 2^18
    const int local = slotbase & (TOT - 1);
    const int count = g_pos[r] - r * TOT;
    if (local >= count) return;
    const int nvalid = min(128, count - local);

    load_bias(smem, tid, b0 + r * 128, b1 + r * 64);

    // gather X: thread = half a row (half 0 = a, half 1 = o)
    {
        const int xrow = tid >> 1;
        const int half = tid & 1;
        if (xrow < nvalid) {
            const int grow = g_perm[slotbase + xrow];
            const float* src = (half ? o : a) + (size_t)grow * 64;
            #pragma unroll
            for (int j = 0; j < 8; j++) {
                float4 v0 = ((const float4*)src)[2 * j];
                float4 v1 = ((const float4*)src)[2 * j + 1];
                uint32_t off = sw_off(xrow, half * 8 + j);
                *(uint4*)(smem + OFF_X + off) = make_uint4(
                    pack2h(v0.x, v0.y), pack2h(v0.z, v0.w),
                    pack2h(v1.x, v1.y), pack2h(v1.z, v1.w));
            }
        } else {
            #pragma unroll
            for (int j = 0; j < 8; j++)
                *(uint4*)(smem + OFF_X + sw_off(xrow, half * 8 + j)) =
                    make_uint4(0, 0, 0, 0);
        }
    }
    __syncthreads();

    float acc2[2][4][4];
    two_layer_mma(smem, smem_base, r, lane, wm2, wn2, acc2);
    __syncthreads();        // all warps done reading X before D2 staging

    // stage D2 (stride 68) into the dead X region
    float* sD2 = (float*)(smem + OFF_X);
    #pragma unroll
    for (int i = 0; i < 2; i++) {
        int row0 = wm2 * 32 + i * 16 + (lane >> 2);
        #pragma unroll
        for (int j = 0; j < 4; j++) {
            int col = wn2 * 32 + j * 8 + 2 * (lane & 3);
            *(float2*)&sD2[row0 * 68 + col] =
                make_float2(acc2[i][j][0], acc2[i][j][1]);
            *(float2*)&sD2[(row0 + 8) * 68 + col] =
                make_float2(acc2[i][j][2], acc2[i][j][3]);
        }
    }
    __syncthreads();

    const float* sb1 = (const float*)(smem + OFF_B1);
    if (tid < nvalid) {
        int grow = g_perm[slotbase + tid];
        const float4* uir = (const float4*)(g_ui + (size_t)(grow >> 5) * 64);
        const float* drow = sD2 + tid * 68;
        float sdot = 0.f;
        #pragma unroll
        for (int c4 = 0; c4 < 16; c4++) {
            float4 uv = uir[c4];
            float v0 = lrelu(drow[4 * c4 + 0] + sb1[4 * c4 + 0]);
            float v1 = lrelu(drow[4 * c4 + 1] + sb1[4 * c4 + 1]);
            float v2 = lrelu(drow[4 * c4 + 2] + sb1[4 * c4 + 2]);
            float v3 = lrelu(drow[4 * c4 + 3] + sb1[4 * c4 + 3]);
            sdot = fmaf(v0, uv.x, sdot); sdot = fmaf(v1, uv.y, sdot);
            sdot = fmaf(v2, uv.z, sdot); sdot = fmaf(v3, uv.w, sdot);
        }
        out[grow] = sdot;
    }
}

// ===========================================================================
extern "C" void kernel_launch(void* const* d_in, const int* in_sizes, int n_in,
                              void* d_out, int out_size) {
    const float* u    = (const float*)d_in[0];
    const float* iv   = (const float*)d_in[1];
    const float* a    = (const float*)d_in[2];
    const float* o    = (const float*)d_in[3];
    const int*   s    = (const int*)  d_in[4];
    const float* aoW0 = (const float*)d_in[5];
    const float* aob0 = (const float*)d_in[6];
    const float* aoW1 = (const float*)d_in[7];
    const float* aob1 = (const float*)d_in[8];
    const float* uiW0 = (const float*)d_in[9];
    const float* uib0 = (const float*)d_in[10];
    const float* uiW1 = (const float*)d_in[11];
    const float* uib1 = (const float*)d_in[12];
    float* out = (float*)d_out;

    cudaFuncSetAttribute((const void*)ui_scatter_kernel,
                         cudaFuncAttributeMaxDynamicSharedMemorySize, SM_BYTES);
    cudaFuncSetAttribute((const void*)ao_mma_kernel,
                         cudaFuncAttributeMaxDynamicSharedMemorySize, SM_BYTES);

    prep_w_kernel<<<192, 256>>>(aoW0, aoW1, uiW0, uiW1);
    ui_scatter_kernel<<<64 + TOT / 256, 256, SM_BYTES>>>(u, iv, uib0, uib1, s);
    ao_mma_kernel<<<3 * TOT / 128, 256, SM_BYTES>>>(a, o, aob0, aob1, out);
}

// round 16
// speedup vs baseline: 1.1403x; 1.0393x over previous
#include <cuda_runtime.h>
#include <cuda_fp16.h>
#include <cstdint>

// Model_53283364274775 on GB300 (plain sm_103 PTX target -> no tcgen05):
// single-pass fp16 mma.sync. R16: 3 CTAs/SM (24 warps) with SMALL smem
// (35.8KB -> L1D ~120KB keeps W-fragment images L1-resident).
// Warps own m16 rows; GEMM1 = 4 passes n32 (acc 16 regs) folded straight
// into register GEMM2 A-fragments; GEMM2 = 2 halves n32 (acc2 16 regs).
// Accumulation order preserved -> bitwise-identical output (oracle).

#define B_   8192
#define N_   32
#define TOT  (B_ * N_)          // 262144 = 2^18
#define SLOPE 0.01f

__device__ int   g_pos[3];
__device__ int   g_perm[3 * TOT];
__device__ float g_ui[B_ * 64];
// W0 B-fragments: [rel][s(4)][kk(8)][p(2)][lane] uint4   (32KB/rel)
__device__ uint4 g_w0frag[4 * 4 * 8 * 2 * 32];
// W1 B-fragments: [rel][hh(2)][kk(8)][p(2)][lane] uint4  (16KB/rel)
__device__ uint4 g_w1frag[4 * 2 * 8 * 2 * 32];

__device__ __forceinline__ float lrelu(float x) { return x >= 0.f ? x : SLOPE * x; }

__device__ __forceinline__ uint32_t smem_to_u32(const void* p) {
    uint32_t a;
    asm("{ .reg .u64 t; cvta.to.shared.u64 t, %1; cvt.u32.u64 %0, t; }"
        : "=r"(a) : "l"(p));
    return a;
}
__device__ __forceinline__ void ldsm_x4(uint32_t& r0, uint32_t& r1,
                                        uint32_t& r2, uint32_t& r3, uint32_t addr) {
    asm volatile("ldmatrix.sync.aligned.m8n8.x4.shared.b16 {%0,%1,%2,%3}, [%4];"
        : "=r"(r0), "=r"(r1), "=r"(r2), "=r"(r3) : "r"(addr));
}
__device__ __forceinline__ void mma_f16(float* d, const uint32_t* a4,
                                        uint32_t b0, uint32_t b1) {
    asm volatile("mma.sync.aligned.m16n8k16.row.col.f32.f16.f16.f32 "
        "{%0,%1,%2,%3}, {%4,%5,%6,%7}, {%8,%9}, {%0,%1,%2,%3};"
        : "+f"(d[0]), "+f"(d[1]), "+f"(d[2]), "+f"(d[3])
        : "r"(a4[0]), "r"(a4[1]), "r"(a4[2]), "r"(a4[3]), "r"(b0), "r"(b1));
}
// 256B rows of fp16, XOR swizzle on 16B chunks: conflict-free ldmatrix
__device__ __forceinline__ uint32_t sw_off(int row, int chunk16) {
    return (uint32_t)(row * 256 + ((chunk16 ^ (row & 7)) << 4));
}
__device__ __forceinline__ uint32_t pack2h(float f0, float f1) {
    return (uint32_t)__half_as_ushort(__float2half_rn(f0)) |
           ((uint32_t)__half_as_ushort(__float2half_rn(f1)) << 16);
}

// smem layout (bytes): b0 @0 (512) | b1 @512 (256) | pad | X @1024 (32K+2K)
// D2 staging (34816B) reuses the X region after GEMM1.
#define OFF_B0   0
#define OFF_B1   512
#define OFF_X    1024
#define SM_BYTES 35840

// ======================= prep_w (+ g_pos init) =============================
__global__ void prep_w_kernel(const float* __restrict__ aoW0,
                              const float* __restrict__ aoW1,
                              const float* __restrict__ uiW0,
                              const float* __restrict__ uiW1) {
    int idx = blockIdx.x * blockDim.x + threadIdx.x;   // 0..49151
    if (blockIdx.x == 0 && threadIdx.x < 3)
        g_pos[threadIdx.x] = threadIdx.x * TOT;

    if (idx < 32768) {
        // W0 frag word: ((((rel*4+s)*8+kk)*2+p)*32+lane)*4+w
        int r = idx >> 13, t = idx & 8191;
        int w    = t & 3;
        int lane = (t >> 2) & 31;
        int p    = (t >> 7) & 1;
        int kk   = (t >> 8) & 7;
        int s    = (t >> 11) & 3;
        const float* W = (r < 3) ? (aoW0 + r * 16384) : uiW0;
        int j = s * 4 + p * 2 + (w >> 1);
        int n = j * 8 + (lane >> 2);
        int k = kk * 16 + (lane & 3) * 2 + (w & 1) * 8;
        uint32_t v = pack2h(W[k * 128 + n], W[(k + 1) * 128 + n]);
        ((uint32_t*)g_w0frag)[(((((size_t)r * 4 + s) * 8 + kk) * 2 + p) * 32 + lane) * 4 + w] = v;
    } else if (idx < 49152) {
        // W1 frag word: ((((rel*2+hh)*8+kk)*2+p)*32+lane)*4+w
        int t2 = idx - 32768;
        int r = t2 >> 12, t = t2 & 4095;
        int w    = t & 3;
        int lane = (t >> 2) & 31;
        int p    = (t >> 7) & 1;
        int kk   = (t >> 8) & 7;
        int hh   = (t >> 11) & 1;
        const float* W = (r < 3) ? (aoW1 + r * 8192) : uiW1;
        int j = hh * 4 + p * 2 + (w >> 1);
        int n = j * 8 + (lane >> 2);
        int k = kk * 16 + (lane & 3) * 2 + (w & 1) * 8;
        uint32_t v = pack2h(W[k * 64 + n], W[(k + 1) * 64 + n]);
        ((uint32_t*)g_w1frag)[(((((size_t)r * 2 + hh) * 8 + kk) * 2 + p) * 32 + lane) * 4 + w] = v;
    }
}

// ======================= GEMM1: X -> register A-fragments of H =============
// Warp wid owns rows 16*wid..+15. 4 passes of n32; per pass acc[4][4].
// Each pass folds D into afrag2 chunks 2s, 2s+1 (bias+lrelu+fp16 pack).
__device__ __forceinline__ void gemm1_reg(
    uint32_t Xb, const float* sb0, int rel, int lane, int wid,
    uint32_t (&afrag2)[8][4])
{
    const int arow = wid * 16 + (lane & 15);
    #pragma unroll
    for (int s = 0; s < 4; s++) {
        float acc[4][4];
        #pragma unroll
        for (int j = 0; j < 4; j++)
            #pragma unroll
            for (int q = 0; q < 4; q++) acc[j][q] = 0.f;

        const uint4* w0p = g_w0frag + (((size_t)rel * 4 + s) * 8) * 2 * 32 + lane;
        #pragma unroll
        for (int kk = 0; kk < 8; kk++) {
            uint4 bq0 = w0p[(kk * 2 + 0) * 32];
            uint4 bq1 = w0p[(kk * 2 + 1) * 32];
            uint32_t af[4];
            ldsm_x4(af[0], af[1], af[2], af[3],
                    Xb + sw_off(arow, kk * 2 + (lane >> 4)));
            mma_f16(acc[0], af, bq0.x, bq0.y);
            mma_f16(acc[1], af, bq0.z, bq0.w);
            mma_f16(acc[2], af, bq1.x, bq1.y);
            mma_f16(acc[3], af, bq1.z, bq1.w);
        }
        #pragma unroll
        for (int q2 = 0; q2 < 2; q2++) {
            int c0 = s * 32 + q2 * 16 + 2 * (lane & 3);
            float b00 = sb0[c0],     b01 = sb0[c0 + 1];
            float b80 = sb0[c0 + 8], b81 = sb0[c0 + 9];
            afrag2[2 * s + q2][0] =
                pack2h(lrelu(acc[2 * q2][0] + b00), lrelu(acc[2 * q2][1] + b01));
            afrag2[2 * s + q2][1] =
                pack2h(lrelu(acc[2 * q2][2] + b00), lrelu(acc[2 * q2][3] + b01));
            afrag2[2 * s + q2][2] =
                pack2h(lrelu(acc[2 * q2 + 1][0] + b80), lrelu(acc[2 * q2 + 1][1] + b81));
            afrag2[2 * s + q2][3] =
                pack2h(lrelu(acc[2 * q2 + 1][2] + b80), lrelu(acc[2 * q2 + 1][3] + b81));
        }
    }
}

// GEMM2 half hh (n32): acc2[4][4] over c=0..7 ascending.
__device__ __forceinline__ void gemm2_half(
    int rel, int hh, int lane, const uint32_t (&afrag2)[8][4],
    float (&acc2)[4][4])
{
    #pragma unroll
    for (int j = 0; j < 4; j++)
        #pragma unroll
        for (int q = 0; q < 4; q++) acc2[j][q] = 0.f;

    const uint4* w1p = g_w1frag + (((size_t)rel * 2 + hh) * 8) * 2 * 32 + lane;
    #pragma unroll
    for (int c = 0; c < 8; c++) {
        uint4 bq0 = w1p[(c * 2 + 0) * 32];
        uint4 bq1 = w1p[(c * 2 + 1) * 32];
        mma_f16(acc2[0], afrag2[c], bq0.x, bq0.y);
        mma_f16(acc2[1], afrag2[c], bq0.z, bq0.w);
        mma_f16(acc2[2], afrag2[c], bq1.x, bq1.y);
        mma_f16(acc2[3], afrag2[c], bq1.z, bq1.w);
    }
}

__device__ __forceinline__ void load_bias(char* smem, int tid,
                                          const float* b0, const float* b1) {
    if (tid < 128) ((float*)(smem + OFF_B0))[tid] = b0[tid];
    if (tid < 64)  ((float*)(smem + OFF_B1))[tid] = b1[tid];
}

// ======================= UI branch + scatter (fused) =======================
__global__ void __launch_bounds__(256, 3) ui_scatter_kernel(
    const float* __restrict__ u, const float* __restrict__ iv,
    const float* __restrict__ b0, const float* __restrict__ b1,
    const int* __restrict__ s_raw)
{
    extern __shared__ char smem[];
    const int tid = threadIdx.x;

    if (blockIdx.x >= 64) {
        // ---- scatter path (warp-aggregated bucket sort) ----
        __shared__ int sIs64;
        if (tid == 0) {
            int nz = 0;
            #pragma unroll
            for (int i = 1; i < 256; i += 2) nz |= s_raw[i];
            sIs64 = (nz == 0) ? 1 : 0;
        }
        __syncthreads();
        int idx = (blockIdx.x - 64) * 256 + tid;
        int lane = tid & 31;
        int r = sIs64 ? s_raw[2 * idx] : s_raw[idx];
        unsigned m0 = __ballot_sync(0xffffffffu, r == 0);
        unsigned m1 = __ballot_sync(0xffffffffu, r == 1);
        unsigned mine = (r == 0) ? m0 : (r == 1) ? m1 : ~(m0 | m1);
        int leader = __ffs(mine) - 1;
        int base = 0;
        if (lane == leader) base = atomicAdd(&g_pos[r], __popc(mine));
        base = __shfl_sync(0xffffffffu, base, leader);
        g_perm[base + __popc(mine & ((1u << lane) - 1u))] = idx;
        return;
    }

    // ---- UI path ----
    const uint32_t smem_base = smem_to_u32(smem);
    const int lane = tid & 31;
    const int wid = tid >> 5;
    const int rowbase = blockIdx.x * 128;

    load_bias(smem, tid, b0, b1);
    {
        const int xrow = tid >> 1;
        const int half = tid & 1;
        const float* src = (half ? iv : u) + (size_t)(rowbase + xrow) * 64;
        #pragma unroll
        for (int j = 0; j < 8; j++) {
            float4 v0 = ((const float4*)src)[2 * j];
            float4 v1 = ((const float4*)src)[2 * j + 1];
            uint32_t off = sw_off(xrow, half * 8 + j);
            *(uint4*)(smem + OFF_X + off) = make_uint4(
                pack2h(v0.x, v0.y), pack2h(v0.z, v0.w),
                pack2h(v1.x, v1.y), pack2h(v1.z, v1.w));
        }
    }
    __syncthreads();

    uint32_t afrag2[8][4];
    gemm1_reg(smem_base + OFF_X, (const float*)(smem + OFF_B0), 3, lane, wid, afrag2);

    const float* sb1 = (const float*)(smem + OFF_B1);
    #pragma unroll
    for (int hh = 0; hh < 2; hh++) {
        float acc2[4][4];
        gemm2_half(3, hh, lane, afrag2, acc2);
        int row0 = wid * 16 + (lane >> 2);
        #pragma unroll
        for (int j = 0; j < 4; j++) {
            int col = hh * 32 + j * 8 + 2 * (lane & 3);
            float bv0 = sb1[col], bv1 = sb1[col + 1];
            *(float2*)&g_ui[(size_t)(rowbase + row0) * 64 + col] =
                make_float2(lrelu(acc2[j][0] + bv0), lrelu(acc2[j][1] + bv1));
            *(float2*)&g_ui[(size_t)(rowbase + row0 + 8) * 64 + col] =
                make_float2(lrelu(acc2[j][2] + bv0), lrelu(acc2[j][3] + bv1));
        }
    }
}

// ======================= AO branch: 128 rows per CTA =======================
// 3*TOT/128 = 6144 CTAs; empty tails exit immediately.
__global__ void __launch_bounds__(256, 3) ao_mma_kernel(
    const float* __restrict__ a, const float* __restrict__ o,
    const float* __restrict__ b0, const float* __restrict__ b1,
    float* __restrict__ out)
{
    extern __shared__ char smem[];
    const uint32_t smem_base = smem_to_u32(smem);
    const int tid = threadIdx.x;
    const int lane = tid & 31;
    const int wid = tid >> 5;
    const int slotbase = blockIdx.x * 128;      // absolute in [0, 3*TOT)
    const int r = slotbase >> 18;               // TOT = 2^18
    const int local = slotbase & (TOT - 1);
    const int count = g_pos[r] - r * TOT;
    if (local >= count) return;
    const int nvalid = min(128, count - local);

    load_bias(smem, tid, b0 + r * 128, b1 + r * 64);

    // gather X: thread = half a row (half 0 = a, half 1 = o)
    {
        const int xrow = tid >> 1;
        const int half = tid & 1;
        if (xrow < nvalid) {
            const int grow = g_perm[slotbase + xrow];
            const float* src = (half ? o : a) + (size_t)grow * 64;
            #pragma unroll
            for (int j = 0; j < 8; j++) {
                float4 v0 = ((const float4*)src)[2 * j];
                float4 v1 = ((const float4*)src)[2 * j + 1];
                uint32_t off = sw_off(xrow, half * 8 + j);
                *(uint4*)(smem + OFF_X + off) = make_uint4(
                    pack2h(v0.x, v0.y), pack2h(v0.z, v0.w),
                    pack2h(v1.x, v1.y), pack2h(v1.z, v1.w));
            }
        } else {
            #pragma unroll
            for (int j = 0; j < 8; j++)
                *(uint4*)(smem + OFF_X + sw_off(xrow, half * 8 + j)) =
                    make_uint4(0, 0, 0, 0);
        }
    }
    __syncthreads();

    uint32_t afrag2[8][4];
    gemm1_reg(smem_base + OFF_X, (const float*)(smem + OFF_B0), r, lane, wid, afrag2);
    __syncthreads();        // all warps done with X before D2 staging

    // GEMM2 halves; stage D2 (stride 68) into dead X region
    float* sD2 = (float*)(smem + OFF_X);
    #pragma unroll
    for (int hh = 0; hh < 2; hh++) {
        float acc2[4][4];
        gemm2_half(r, hh, lane, afrag2, acc2);
        int row0 = wid * 16 + (lane >> 2);
        #pragma unroll
        for (int j = 0; j < 4; j++) {
            int col = hh * 32 + j * 8 + 2 * (lane & 3);
            *(float2*)&sD2[row0 * 68 + col] =
                make_float2(acc2[j][0], acc2[j][1]);
            *(float2*)&sD2[(row0 + 8) * 68 + col] =
                make_float2(acc2[j][2], acc2[j][3]);
        }
    }
    __syncthreads();

    const float* sb1 = (const float*)(smem + OFF_B1);
    if (tid < nvalid) {
        int grow = g_perm[slotbase + tid];
        const float4* uir = (const float4*)(g_ui + (size_t)(grow >> 5) * 64);
        const float* drow = sD2 + tid * 68;
        float sdot = 0.f;
        #pragma unroll
        for (int c4 = 0; c4 < 16; c4++) {
            float4 uv = uir[c4];
            float v0 = lrelu(drow[4 * c4 + 0] + sb1[4 * c4 + 0]);
            float v1 = lrelu(drow[4 * c4 + 1] + sb1[4 * c4 + 1]);
            float v2 = lrelu(drow[4 * c4 + 2] + sb1[4 * c4 + 2]);
            float v3 = lrelu(drow[4 * c4 + 3] + sb1[4 * c4 + 3]);
            sdot = fmaf(v0, uv.x, sdot); sdot = fmaf(v1, uv.y, sdot);
            sdot = fmaf(v2, uv.z, sdot); sdot = fmaf(v3, uv.w, sdot);
        }
        out[grow] = sdot;
    }
}

// ===========================================================================
extern "C" void kernel_launch(void* const* d_in, const int* in_sizes, int n_in,
                              void* d_out, int out_size) {
    const float* u    = (const float*)d_in[0];
    const float* iv   = (const float*)d_in[1];
    const float* a    = (const float*)d_in[2];
    const float* o    = (const float*)d_in[3];
    const int*   s    = (const int*)  d_in[4];
    const float* aoW0 = (const float*)d_in[5];
    const float* aob0 = (const float*)d_in[6];
    const float* aoW1 = (const float*)d_in[7];
    const float* aob1 = (const float*)d_in[8];
    const float* uiW0 = (const float*)d_in[9];
    const float* uib0 = (const float*)d_in[10];
    const float* uiW1 = (const float*)d_in[11];
    const float* uib1 = (const float*)d_in[12];
    float* out = (float*)d_out;

    cudaFuncSetAttribute((const void*)ui_scatter_kernel,
                         cudaFuncAttributeMaxDynamicSharedMemorySize, SM_BYTES);
    cudaFuncSetAttribute((const void*)ao_mma_kernel,
                         cudaFuncAttributeMaxDynamicSharedMemorySize, SM_BYTES);

    prep_w_kernel<<<192, 256>>>(aoW0, aoW1, uiW0, uiW1);
    ui_scatter_kernel<<<64 + TOT / 256, 256, SM_BYTES>>>(u, iv, uib0, uib1, s);
    ao_mma_kernel<<<3 * TOT / 128, 256, SM_BYTES>>>(a, o, aob0, aob1, out);
}

// round 17
// speedup vs baseline: 1.2410x; 1.0883x over previous
#include <cuda_runtime.h>
#include <cuda_fp16.h>
#include <cstdint>

// Model_53283364274775 on GB300 (plain sm_103 PTX target -> no tcgen05):
// single-pass fp16 mma.sync. R17: persistent AO CTAs (grid 304, 2/SM),
// double-buffered block pipeline: next block's X gather + bias issue into
// the alternate smem buffer BEFORE current block's GEMMs, hiding DRAM
// gather latency behind MMA. R13 register-H core (bitwise-identical math).

#define B_   8192
#define N_   32
#define TOT  (B_ * N_)          // 262144 = 2^18
#define SLOPE 0.01f
#define NSLOT (3 * TOT / 128)   // 6144 slot-blocks
#define NPERS 304               // persistent CTAs (2 per SM)

__device__ int   g_pos[3];
__device__ int   g_perm[3 * TOT];
__device__ float g_ui[B_ * 64];
// W0 B-fragments: [rel][kk(8)][j2(8)][lane] uint4  (32KB/rel)
__device__ uint4 g_w0frag[4 * 8 * 8 * 32];
// W1 B-fragments: [rel][kk(8)][q(4)][lane] uint4   (16KB/rel)
__device__ uint4 g_w1frag[4 * 8 * 4 * 32];

__device__ __forceinline__ float lrelu(float x) { return x >= 0.f ? x : SLOPE * x; }

__device__ __forceinline__ uint32_t smem_to_u32(const void* p) {
    uint32_t a;
    asm("{ .reg .u64 t; cvta.to.shared.u64 t, %1; cvt.u32.u64 %0, t; }"
        : "=r"(a) : "l"(p));
    return a;
}
__device__ __forceinline__ void ldsm_x4(uint32_t& r0, uint32_t& r1,
                                        uint32_t& r2, uint32_t& r3, uint32_t addr) {
    asm volatile("ldmatrix.sync.aligned.m8n8.x4.shared.b16 {%0,%1,%2,%3}, [%4];"
        : "=r"(r0), "=r"(r1), "=r"(r2), "=r"(r3) : "r"(addr));
}
__device__ __forceinline__ void mma_f16(float* d, const uint32_t* a4,
                                        uint32_t b0, uint32_t b1) {
    asm volatile("mma.sync.aligned.m16n8k16.row.col.f32.f16.f16.f32 "
        "{%0,%1,%2,%3}, {%4,%5,%6,%7}, {%8,%9}, {%0,%1,%2,%3};"
        : "+f"(d[0]), "+f"(d[1]), "+f"(d[2]), "+f"(d[3])
        : "r"(a4[0]), "r"(a4[1]), "r"(a4[2]), "r"(a4[3]), "r"(b0), "r"(b1));
}
// 256B rows of fp16, XOR swizzle on 16B chunks: conflict-free ldmatrix
__device__ __forceinline__ uint32_t sw_off(int row, int chunk16) {
    return (uint32_t)(row * 256 + ((chunk16 ^ (row & 7)) << 4));
}
__device__ __forceinline__ uint32_t pack2h(float f0, float f1) {
    return (uint32_t)__half_as_ushort(__float2half_rn(f0)) |
           ((uint32_t)__half_as_ushort(__float2half_rn(f1)) << 16);
}

// per-buffer smem layout (bytes): b0 @0 (512) | b1 @512 (256) | pad |
// X @1024 (32K + 2K pad).  Buffer size 36KB; AO uses two buffers.
#define BUFSZ    36864
#define OFF_B0   0
#define OFF_B1   512
#define OFF_X    1024
#define SM_UI    36864
#define SM_AO    73728

// ======================= prep_w (+ g_pos init) =============================
__global__ void prep_w_kernel(const float* __restrict__ aoW0,
                              const float* __restrict__ aoW1,
                              const float* __restrict__ uiW0,
                              const float* __restrict__ uiW1) {
    int idx = blockIdx.x * blockDim.x + threadIdx.x;   // 0..49151
    if (blockIdx.x == 0 && threadIdx.x < 3)
        g_pos[threadIdx.x] = threadIdx.x * TOT;

    if (idx < 32768) {
        // W0 frag word: (((rel*8+kk)*8 + j2)*32 + lane)*4 + w
        int r = idx >> 13, t = idx & 8191;
        int w    = t & 3;
        int lane = (t >> 2) & 31;
        int j2   = (t >> 7) & 7;
        int kk   = (t >> 10) & 7;
        const float* W = (r < 3) ? (aoW0 + r * 16384) : uiW0;
        int j = 2 * j2 + (w >> 1);
        int n = j * 8 + (lane >> 2);
        int k = kk * 16 + (lane & 3) * 2 + (w & 1) * 8;
        uint32_t v = pack2h(W[k * 128 + n], W[(k + 1) * 128 + n]);
        ((uint32_t*)g_w0frag)[((((size_t)r * 8 + kk) * 8 + j2) * 32 + lane) * 4 + w] = v;
    } else if (idx < 49152) {
        // W1 frag word: (((rel*8+kk)*4 + q)*32 + lane)*4 + w
        int t2 = idx - 32768;
        int r = t2 >> 12, t = t2 & 4095;
        int w    = t & 3;
        int lane = (t >> 2) & 31;
        int q    = (t >> 7) & 3;
        int kk   = (t >> 9) & 7;
        const float* W = (r < 3) ? (aoW1 + r * 8192) : uiW1;
        int j = 2 * q + (w >> 1);
        int n = j * 8 + (lane >> 2);
        int k = kk * 16 + (lane & 3) * 2 + (w & 1) * 8;
        uint32_t v = pack2h(W[k * 64 + n], W[(k + 1) * 64 + n]);
        ((uint32_t*)g_w1frag)[((((size_t)r * 8 + kk) * 4 + q) * 32 + lane) * 4 + w] = v;
    }
}

// ======================= core: two layers, register H (R13) ================
__device__ __forceinline__ void two_layer_reg(
    char* smem, uint32_t smem_base, int rel, int lane, int wid,
    uint32_t bufoff, float (&acc2)[8][4])
{
    const float* sb0 = (const float*)(smem + bufoff + OFF_B0);
    uint32_t afrag2[8][4];
    const uint32_t Ab = smem_base + bufoff + OFF_X;
    const int arow = wid * 16 + (lane & 15);

    #pragma unroll
    for (int h = 0; h < 2; h++) {
        float acc[8][4];
        #pragma unroll
        for (int j = 0; j < 8; j++)
            #pragma unroll
            for (int q = 0; q < 4; q++) acc[j][q] = 0.f;

        const uint4* w0p = g_w0frag + (((size_t)rel * 8) * 8 + h * 4) * 32 + lane;
        #pragma unroll
        for (int kk = 0; kk < 8; kk++) {
            uint4 bq[4];
            #pragma unroll
            for (int q = 0; q < 4; q++) bq[q] = w0p[(kk * 8 + q) * 32];
            uint32_t af[4];
            ldsm_x4(af[0], af[1], af[2], af[3],
                    Ab + sw_off(arow, kk * 2 + (lane >> 4)));
            #pragma unroll
            for (int j = 0; j < 8; j++)
                mma_f16(acc[j], af,
                        (j & 1) ? bq[j >> 1].z : bq[j >> 1].x,
                        (j & 1) ? bq[j >> 1].w : bq[j >> 1].y);
        }

        #pragma unroll
        for (int q2 = 0; q2 < 4; q2++) {
            int c0 = h * 64 + q2 * 16 + 2 * (lane & 3);
            float b00 = sb0[c0],     b01 = sb0[c0 + 1];
            float b80 = sb0[c0 + 8], b81 = sb0[c0 + 9];
            afrag2[h * 4 + q2][0] =
                pack2h(lrelu(acc[2 * q2][0] + b00), lrelu(acc[2 * q2][1] + b01));
            afrag2[h * 4 + q2][1] =
                pack2h(lrelu(acc[2 * q2][2] + b00), lrelu(acc[2 * q2][3] + b01));
            afrag2[h * 4 + q2][2] =
                pack2h(lrelu(acc[2 * q2 + 1][0] + b80), lrelu(acc[2 * q2 + 1][1] + b81));
            afrag2[h * 4 + q2][3] =
                pack2h(lrelu(acc[2 * q2 + 1][2] + b80), lrelu(acc[2 * q2 + 1][3] + b81));
        }
    }

    #pragma unroll
    for (int j = 0; j < 8; j++)
        #pragma unroll
        for (int q = 0; q < 4; q++) acc2[j][q] = 0.f;

    const uint4* w1p = g_w1frag + ((size_t)rel * 8) * 4 * 32 + lane;
    #pragma unroll
    for (int c = 0; c < 8; c++) {
        uint4 bq[4];
        #pragma unroll
        for (int q = 0; q < 4; q++) bq[q] = w1p[(c * 4 + q) * 32];
        #pragma unroll
        for (int j = 0; j < 8; j++)
            mma_f16(acc2[j], afrag2[c],
                    (j & 1) ? bq[j >> 1].z : bq[j >> 1].x,
                    (j & 1) ? bq[j >> 1].w : bq[j >> 1].y);
    }
}

// gather one block's X (+bias) into buffer bufoff
__device__ __forceinline__ void gather_block(
    char* smem, uint32_t bufoff, int slotbase, int nvalid, int rel, int tid,
    const float* a, const float* o, const float* b0, const float* b1)
{
    if (tid < 128) ((float*)(smem + bufoff + OFF_B0))[tid] = b0[rel * 128 + tid];
    if (tid < 64)  ((float*)(smem + bufoff + OFF_B1))[tid] = b1[rel * 64 + tid];
    const int xrow = tid >> 1;
    const int half = tid & 1;
    if (xrow < nvalid) {
        const int grow = g_perm[slotbase + xrow];
        const float* src = (half ? o : a) + (size_t)grow * 64;
        #pragma unroll
        for (int j = 0; j < 8; j++) {
            float4 v0 = ((const float4*)src)[2 * j];
            float4 v1 = ((const float4*)src)[2 * j + 1];
            uint32_t off = sw_off(xrow, half * 8 + j);
            *(uint4*)(smem + bufoff + OFF_X + off) = make_uint4(
                pack2h(v0.x, v0.y), pack2h(v0.z, v0.w),
                pack2h(v1.x, v1.y), pack2h(v1.z, v1.w));
        }
    } else {
        #pragma unroll
        for (int j = 0; j < 8; j++)
            *(uint4*)(smem + bufoff + OFF_X + sw_off(xrow, half * 8 + j)) =
                make_uint4(0, 0, 0, 0);
    }
}

// ======================= UI branch + scatter (fused) =======================
__global__ void __launch_bounds__(256, 2) ui_scatter_kernel(
    const float* __restrict__ u, const float* __restrict__ iv,
    const float* __restrict__ b0, const float* __restrict__ b1,
    const int* __restrict__ s_raw)
{
    extern __shared__ char smem[];
    const int tid = threadIdx.x;

    if (blockIdx.x >= 64) {
        // ---- scatter path (warp-aggregated bucket sort) ----
        __shared__ int sIs64;
        if (tid == 0) {
            int nz = 0;
            #pragma unroll
            for (int i = 1; i < 256; i += 2) nz |= s_raw[i];
            sIs64 = (nz == 0) ? 1 : 0;
        }
        __syncthreads();
        int idx = (blockIdx.x - 64) * 256 + tid;
        int lane = tid & 31;
        int r = sIs64 ? s_raw[2 * idx] : s_raw[idx];
        unsigned m0 = __ballot_sync(0xffffffffu, r == 0);
        unsigned m1 = __ballot_sync(0xffffffffu, r == 1);
        unsigned mine = (r == 0) ? m0 : (r == 1) ? m1 : ~(m0 | m1);
        int leader = __ffs(mine) - 1;
        int base = 0;
        if (lane == leader) base = atomicAdd(&g_pos[r], __popc(mine));
        base = __shfl_sync(0xffffffffu, base, leader);
        g_perm[base + __popc(mine & ((1u << lane) - 1u))] = idx;
        return;
    }

    // ---- UI path ----
    const uint32_t smem_base = smem_to_u32(smem);
    const int lane = tid & 31;
    const int wid = tid >> 5;
    const int rowbase = blockIdx.x * 128;

    if (tid < 128) ((float*)(smem + OFF_B0))[tid] = b0[tid];
    if (tid < 64)  ((float*)(smem + OFF_B1))[tid] = b1[tid];
    {
        const int xrow = tid >> 1;
        const int half = tid & 1;
        const float* src = (half ? iv : u) + (size_t)(rowbase + xrow) * 64;
        #pragma unroll
        for (int j = 0; j < 8; j++) {
            float4 v0 = ((const float4*)src)[2 * j];
            float4 v1 = ((const float4*)src)[2 * j + 1];
            uint32_t off = sw_off(xrow, half * 8 + j);
            *(uint4*)(smem + OFF_X + off) = make_uint4(
                pack2h(v0.x, v0.y), pack2h(v0.z, v0.w),
                pack2h(v1.x, v1.y), pack2h(v1.z, v1.w));
        }
    }
    __syncthreads();

    float acc2[8][4];
    two_layer_reg(smem, smem_base, 3, lane, wid, 0, acc2);

    const float* sb1 = (const float*)(smem + OFF_B1);
    int row0 = wid * 16 + (lane >> 2);
    #pragma unroll
    for (int j = 0; j < 8; j++) {
        int col = j * 8 + 2 * (lane & 3);
        float bv0 = sb1[col], bv1 = sb1[col + 1];
        *(float2*)&g_ui[(size_t)(rowbase + row0) * 64 + col] =
            make_float2(lrelu(acc2[j][0] + bv0), lrelu(acc2[j][1] + bv1));
        *(float2*)&g_ui[(size_t)(rowbase + row0 + 8) * 64 + col] =
            make_float2(lrelu(acc2[j][2] + bv0), lrelu(acc2[j][3] + bv1));
    }
}

// ======================= AO: persistent double-buffered ====================
__global__ void __launch_bounds__(256, 2) ao_persist_kernel(
    const float* __restrict__ a, const float* __restrict__ o,
    const float* __restrict__ b0, const float* __restrict__ b1,
    float* __restrict__ out)
{
    extern __shared__ char smem[];
    const uint32_t smem_base = smem_to_u32(smem);
    const int tid = threadIdx.x;
    const int lane = tid & 31;
    const int wid = tid >> 5;

    // bucket counts (final; scatter kernel completed)
    const int c0 = g_pos[0];
    const int c1 = g_pos[1] - TOT;
    const int c2 = g_pos[2] - 2 * TOT;

    // slot -> (valid, rel, nvalid); uniform arithmetic
    auto slot_info = [&](int slot, int& rel, int& nvalid) -> bool {
        int sb = slot * 128;
        int r = sb >> 18;
        int local = sb & (TOT - 1);
        int cnt = (r == 0) ? c0 : (r == 1) ? c1 : c2;
        if (local >= cnt) return false;
        rel = r;
        nvalid = min(128, cnt - local);
        return true;
    };
    auto next_slot = [&](int slot) -> int {
        int rel, nv;
        slot += NPERS;
        while (slot < NSLOT && !slot_info(slot, rel, nv)) slot += NPERS;
        return slot;
    };

    // first non-empty slot for this CTA
    int cur = blockIdx.x;
    {
        int rel, nv;
        while (cur < NSLOT && !slot_info(cur, rel, nv)) cur += NPERS;
    }
    if (cur >= NSLOT) return;

    int pb = 0;
    {   // prologue: gather first block into buf0
        int rel, nv;
        slot_info(cur, rel, nv);
        gather_block(smem, 0, cur * 128, nv, rel, tid, a, o, b0, b1);
    }
    __syncthreads();

    while (cur < NSLOT) {
        int rel, nvalid;
        slot_info(cur, rel, nvalid);
        const uint32_t bufoff = (uint32_t)pb * BUFSZ;

        // prefetch next block into the other buffer (overlaps with compute)
        int nxt = next_slot(cur);
        if (nxt < NSLOT) {
            int nrel, nnv;
            slot_info(nxt, nrel, nnv);
            gather_block(smem, bufoff ^ BUFSZ, nxt * 128, nnv, nrel, tid,
                         a, o, b0, b1);
        }

        // compute current block
        float acc2[8][4];
        two_layer_reg(smem, smem_base, rel, lane, wid, bufoff, acc2);
        __syncthreads();                 // all warps done reading X(cur)

        // stage D2 (stride 68) into current (dead) X buffer
        float* sD2 = (float*)(smem + bufoff + OFF_X);
        {
            int row0 = wid * 16 + (lane >> 2);
            #pragma unroll
            for (int j = 0; j < 8; j++) {
                int col = j * 8 + 2 * (lane & 3);
                *(float2*)&sD2[row0 * 68 + col] =
                    make_float2(acc2[j][0], acc2[j][1]);
                *(float2*)&sD2[(row0 + 8) * 68 + col] =
                    make_float2(acc2[j][2], acc2[j][3]);
            }
        }
        __syncthreads();

        const float* sb1 = (const float*)(smem + bufoff + OFF_B1);
        if (tid < nvalid) {
            int grow = g_perm[cur * 128 + tid];
            const float4* uir = (const float4*)(g_ui + (size_t)(grow >> 5) * 64);
            const float* drow = sD2 + tid * 68;
            float sdot = 0.f;
            #pragma unroll
            for (int c4 = 0; c4 < 16; c4++) {
                float4 uv = uir[c4];
                float v0 = lrelu(drow[4 * c4 + 0] + sb1[4 * c4 + 0]);
                float v1 = lrelu(drow[4 * c4 + 1] + sb1[4 * c4 + 1]);
                float v2 = lrelu(drow[4 * c4 + 2] + sb1[4 * c4 + 2]);
                float v3 = lrelu(drow[4 * c4 + 3] + sb1[4 * c4 + 3]);
                sdot = fmaf(v0, uv.x, sdot); sdot = fmaf(v1, uv.y, sdot);
                sdot = fmaf(v2, uv.z, sdot); sdot = fmaf(v3, uv.w, sdot);
            }
            out[grow] = sdot;
        }
        __syncthreads();   // D2 reads done; prefetched buffer visible to all

        cur = nxt;
        pb ^= 1;
    }
}

// ===========================================================================
extern "C" void kernel_launch(void* const* d_in, const int* in_sizes, int n_in,
                              void* d_out, int out_size) {
    const float* u    = (const float*)d_in[0];
    const float* iv   = (const float*)d_in[1];
    const float* a    = (const float*)d_in[2];
    const float* o    = (const float*)d_in[3];
    const int*   s    = (const int*)  d_in[4];
    const float* aoW0 = (const float*)d_in[5];
    const float* aob0 = (const float*)d_in[6];
    const float* aoW1 = (const float*)d_in[7];
    const float* aob1 = (const float*)d_in[8];
    const float* uiW0 = (const float*)d_in[9];
    const float* uib0 = (const float*)d_in[10];
    const float* uiW1 = (const float*)d_in[11];
    const float* uib1 = (const float*)d_in[12];
    float* out = (float*)d_out;

    cudaFuncSetAttribute((const void*)ui_scatter_kernel,
                         cudaFuncAttributeMaxDynamicSharedMemorySize, SM_UI);
    cudaFuncSetAttribute((const void*)ao_persist_kernel,
                         cudaFuncAttributeMaxDynamicSharedMemorySize, SM_AO);

    prep_w_kernel<<<192, 256>>>(aoW0, aoW1, uiW0, uiW1);
    ui_scatter_kernel<<<64 + TOT / 256, 256, SM_UI>>>(u, iv, uib0, uib1, s);
    ao_persist_kernel<<<NPERS, 256, SM_AO>>>(a, o, aob0, aob1, out);
}